// round 6
// baseline (speedup 1.0000x reference)
#include <cuda_runtime.h>
#include <cuda_fp16.h>
#include <cstdint>
#include <cstddef>

#define DINL __device__ __forceinline__

static constexpr int M_TOTAL = 16384;
static constexpr int D_IN    = 512;
static constexpr int D_OUT   = 128;
static constexpr int KSPLIT  = 8;
static constexpr int KUNIT   = M_TOTAL / KSPLIT;              // 2048 K per unit
static constexpr int UNITS   = (M_TOTAL / 128) * KSPLIT;      // 1024 units

// Static scratch (allocation-free).
// xT / WT are stored K-interleaved per 16-group: {0,1,8,9,2,3,10,11,4,5,12,13,6,7,14,15}
// so one LDG.64 yields the (b0,b1) m16n8k16 B fragment pair.
__device__ __half g_xT[(size_t)D_OUT * M_TOTAL];
__device__ __half g_WT[(size_t)D_OUT * D_IN];
__device__ float  g_part[(size_t)KSPLIT * M_TOTAL * D_OUT];
__device__ unsigned g_ticket;

// ---------------------------------------------------------------- helpers
DINL uint32_t pack_h2(float lo, float hi) {   // low half = lo
    uint32_t r;
    asm("cvt.rn.f16x2.f32 %0, %1, %2;" : "=r"(r) : "f"(hi), "f"(lo));
    return r;
}
DINL void mma_f16(float* c, const uint32_t* a, const uint32_t* b) {
    asm volatile(
        "mma.sync.aligned.m16n8k16.row.col.f32.f16.f16.f32 "
        "{%0,%1,%2,%3}, {%4,%5,%6,%7}, {%8,%9}, {%0,%1,%2,%3};"
        : "+f"(c[0]), "+f"(c[1]), "+f"(c[2]), "+f"(c[3])
        : "r"(a[0]), "r"(a[1]), "r"(a[2]), "r"(a[3]), "r"(b[0]), "r"(b[1]));
}
// slot of k_local (0..15) inside the interleaved 16-group
DINL int kslot(int kl) {
    return ((kl & 7) >> 1) * 4 + (kl & 1) + ((kl >> 3) & 1) * 2;
}

// ---------------------------------------------------------------- kernels
// W[512][128] -> WT fp16 [128][512], K-interleaved; resets ticket.
__global__ void transposeW_kernel(const float* __restrict__ W, __half* __restrict__ WT) {
    if (blockIdx.x == 0 && threadIdx.x == 0) g_ticket = 0u;
    int t = blockIdx.x * blockDim.x + threadIdx.x;   // 65536 threads
    int k = t >> 7, n = t & 127;
    WT[(size_t)n * D_IN + (k & ~15) + kslot(k & 15)] =
        __float2half_rn(W[(size_t)k * D_OUT + n]);
}

// Barrier-free GEMM: C-tile = A[128,K](fp32) @ B[128,K](fp16, K-interleaved)^T.
// Fragments built straight from gmem LDGs (no smem). Warp grid 4x2, tile 32x64.
// QUEUE: persistent ticket (mt, ks) -> g_part.  TRANS_EPI: write C^T fp16 interleaved.
template <int K, bool TRANS_EPI, bool QUEUE>
__global__ void __launch_bounds__(256, 2)
gemm_ldg(const float* __restrict__ A, const __half* __restrict__ B,
         float* __restrict__ C)
{
    __shared__ unsigned s_unit;
    const int tid  = threadIdx.x;
    const int wid  = tid >> 5, lane = tid & 31;
    const int mw   = (wid >> 1) * 32;       // 4 m-groups
    const int nw   = (wid & 1) * 64;        // 2 n-groups
    const int rg   = lane >> 2;             // row/col group 0..7
    const int tq   = lane & 3;              // k quad index
    const int cc   = tq * 2;
    constexpr int STEPS = (QUEUE ? KUNIT : K) / 16;

    for (;;) {
        int mt, ks;
        if (QUEUE) {
            if (tid == 0) s_unit = atomicAdd(&g_ticket, 1u);
            __syncthreads();
            unsigned u = s_unit;
            __syncthreads();                // all threads read before next overwrite
            if (u >= (unsigned)UNITS) return;
            mt = (int)(u & 127u); ks = (int)(u >> 7);
        } else {
            mt = blockIdx.x; ks = 0;
        }
        const int k0 = ks * KUNIT;

        const float* ap = A + (size_t)(mt * 128 + mw + rg) * K + k0 + cc;
        const char*  bp = (const char*)B + ((size_t)(nw + rg) * K + k0) * 2 + tq * 8;
        const float* pp = A + (size_t)(mt * 128 + mw + lane) * K + k0 + 32;

        float acc[2][8][4];
#pragma unroll
        for (int i = 0; i < 2; ++i)
#pragma unroll
            for (int j = 0; j < 8; ++j)
#pragma unroll
                for (int f = 0; f < 4; ++f) acc[i][j][f] = 0.f;

        float2 an[8];           // next-step A fragments (fp32)
#define LD_AN()                                                              \
        do {                                                                 \
            an[0] = *(const float2*)(ap);                                    \
            an[1] = *(const float2*)(ap + (size_t)8  * K);                   \
            an[2] = *(const float2*)(ap + 8);                                \
            an[3] = *(const float2*)(ap + (size_t)8  * K + 8);               \
            an[4] = *(const float2*)(ap + (size_t)16 * K);                   \
            an[5] = *(const float2*)(ap + (size_t)24 * K);                   \
            an[6] = *(const float2*)(ap + (size_t)16 * K + 8);               \
            an[7] = *(const float2*)(ap + (size_t)24 * K + 8);               \
        } while (0)

        LD_AN();                // step 0
        ap += 16;

#pragma unroll 2
        for (int s = 0; s < STEPS; ++s) {
            // B fragments for this step: one LDG.64 per n-tile (interleaved layout)
            uint2 b[8];
#pragma unroll
            for (int j = 0; j < 8; ++j)
                b[j] = *(const uint2*)(bp + (size_t)j * (8 * K * 2));
            // convert current A (loaded last iteration)
            uint32_t a[2][4];
#pragma unroll
            for (int i = 0; i < 2; ++i)
#pragma unroll
                for (int q = 0; q < 4; ++q)
                    a[i][q] = pack_h2(an[i * 4 + q].x, an[i * 4 + q].y);
            // issue next A loads + L2 prefetch (overlap with mma)
            if (s + 1 < STEPS) LD_AN();
            ap += 16;
            if (s + 2 < STEPS)
                asm volatile("prefetch.global.L2 [%0];" :: "l"(pp));
            pp += 16;
            bp += 32;
#pragma unroll
            for (int i = 0; i < 2; ++i)
#pragma unroll
                for (int j = 0; j < 8; ++j)
                    mma_f16(acc[i][j], a[i], (const uint32_t*)&b[j]);
        }
#undef LD_AN

        // Epilogue
#pragma unroll
        for (int i = 0; i < 2; ++i) {
            const int rloc = mw + i * 16 + rg;
#pragma unroll
            for (int j = 0; j < 8; ++j) {
                const int col = nw + j * 8 + cc;
                if (TRANS_EPI) {
                    __half* X = (__half*)C;
                    const int gbase = (mt * 128 + mw + i * 16) & ~15; // 16-aligned
                    const int s0 = kslot(rg);        // slot for row rg
                    const int s1 = kslot(rg + 8);    // slot for row rg+8
                    X[(size_t)col       * M_TOTAL + gbase + s0] = __float2half_rn(acc[i][j][0]);
                    X[(size_t)(col + 1) * M_TOTAL + gbase + s0] = __float2half_rn(acc[i][j][1]);
                    X[(size_t)col       * M_TOTAL + gbase + s1] = __float2half_rn(acc[i][j][2]);
                    X[(size_t)(col + 1) * M_TOTAL + gbase + s1] = __float2half_rn(acc[i][j][3]);
                } else {
                    float* cb = C + ((size_t)ks * M_TOTAL + (size_t)mt * 128) * D_OUT;
                    *(float2*)(cb + (size_t)rloc * D_OUT + col) =
                        make_float2(acc[i][j][0], acc[i][j][1]);
                    *(float2*)(cb + (size_t)(rloc + 8) * D_OUT + col) =
                        make_float2(acc[i][j][2], acc[i][j][3]);
                }
            }
        }
        if (!QUEUE) return;
    }
}

// out = sum over KSPLIT partials
__global__ void reduce_kernel(float* __restrict__ out) {
    const size_t i = (size_t)blockIdx.x * blockDim.x + threadIdx.x;  // 524288 f4
    const float4* p = reinterpret_cast<const float4*>(g_part);
    const size_t stride = (size_t)M_TOTAL * D_OUT / 4;
    float4 s = p[i];
#pragma unroll
    for (int k = 1; k < KSPLIT; ++k) {
        float4 t = p[i + (size_t)k * stride];
        s.x += t.x; s.y += t.y; s.z += t.z; s.w += t.w;
    }
    reinterpret_cast<float4*>(out)[i] = s;
}

// ---------------------------------------------------------------- launch
extern "C" void kernel_launch(void* const* d_in, const int* in_sizes, int n_in,
                              void* d_out, int out_size)
{
    const float* inputs = nullptr;
    const float* adj = nullptr;
    const float* weights = nullptr;
    for (int i = 0; i < n_in; ++i) {
        long sz = (long)in_sizes[i];
        if (sz == (long)M_TOTAL * D_IN)         inputs  = (const float*)d_in[i];
        else if (sz == (long)M_TOTAL * M_TOTAL) adj     = (const float*)d_in[i];
        else if (sz == (long)D_IN * D_OUT)      weights = (const float*)d_in[i];
    }

    __half *xT = nullptr, *WT = nullptr;
    float  *part = nullptr;
    cudaGetSymbolAddress((void**)&xT, g_xT);
    cudaGetSymbolAddress((void**)&WT, g_WT);
    cudaGetSymbolAddress((void**)&part, g_part);

    // 1) WT = fp16(W^T), K-interleaved; reset ticket
    transposeW_kernel<<<(D_IN * D_OUT) / 256, 256>>>(weights, WT);
    // 2) xT = fp16((inputs @ W)^T), K-interleaved
    gemm_ldg<D_IN, true, false><<<M_TOTAL / 128, 256>>>(inputs, WT, (float*)xT);
    // 3) partials = adj @ x  (persistent, barrier-free, split-K=8)
    gemm_ldg<M_TOTAL, false, true><<<296, 256>>>(adj, xT, part);
    // 4) out = sum partials
    reduce_kernel<<<(M_TOTAL * D_OUT / 4) / 256, 256>>>((float*)d_out);
}

// round 7
// speedup vs baseline: 1.8905x; 1.8905x over previous
#include <cuda_runtime.h>
#include <cuda_fp16.h>
#include <cstdint>
#include <cstddef>

#define DINL __device__ __forceinline__

static constexpr int KCHUNK   = 32;              // K elems per chunk
static constexpr int ROW_B    = 80;              // smem row stride bytes (64B data + 16 pad)
static constexpr int TILE_B   = 128 * ROW_B;     // 10240 B per fp16 tile
static constexpr int A_STAGES = 2;
static constexpr int B_STAGES = 4;
static constexpr int SMEM_BYTES = (A_STAGES + B_STAGES) * TILE_B;   // 61440 -> 2 CTAs/SM

static constexpr int M_TOTAL = 16384;
static constexpr int D_IN    = 512;
static constexpr int D_OUT   = 128;
static constexpr int KSPLIT  = 8;
static constexpr int CH_UNIT = (M_TOTAL / KCHUNK) / KSPLIT;   // 64 chunks / unit
static constexpr int UNITS   = (M_TOTAL / 128) * KSPLIT;      // 1024 units

// Static scratch (allocation-free).
__device__ __half g_xT[(size_t)D_OUT * M_TOTAL];              // x^T fp16 [128][16384]
__device__ __half g_WT[(size_t)D_OUT * D_IN];                 // W^T fp16 [128][512]
__device__ float  g_part[(size_t)KSPLIT * M_TOTAL * D_OUT];   // split-K partials
__device__ unsigned g_ticket;

// ---------------------------------------------------------------- helpers
DINL uint32_t smem_u32(const void* p) {
    uint32_t a;
    asm("{ .reg .u64 t; cvta.to.shared.u64 t, %1; cvt.u32.u64 %0, t; }"
        : "=r"(a) : "l"(p));
    return a;
}
DINL void cp16(uint32_t saddr, const void* g) {
    asm volatile("cp.async.cg.shared.global [%0], [%1], 16;"
                 :: "r"(saddr), "l"(g));
}
DINL uint32_t pack_h2(float lo, float hi) {    // low half = lo
    uint32_t r;
    asm("cvt.rn.f16x2.f32 %0, %1, %2;" : "=r"(r) : "f"(hi), "f"(lo));
    return r;
}
DINL void sts64(uint32_t a, uint32_t w0, uint32_t w1) {
    asm volatile("st.shared.v2.b32 [%0], {%1, %2};" :: "r"(a), "r"(w0), "r"(w1) : "memory");
}
DINL void ldsm4(uint32_t* r, uint32_t addr) {
    asm volatile("ldmatrix.sync.aligned.m8n8.x4.shared.b16 {%0,%1,%2,%3}, [%4];"
                 : "=r"(r[0]), "=r"(r[1]), "=r"(r[2]), "=r"(r[3]) : "r"(addr));
}
DINL void mma_f16(float* c, const uint32_t* a, const uint32_t* b) {
    asm volatile(
        "mma.sync.aligned.m16n8k16.row.col.f32.f16.f16.f32 "
        "{%0,%1,%2,%3}, {%4,%5,%6,%7}, {%8,%9}, {%0,%1,%2,%3};"
        : "+f"(c[0]), "+f"(c[1]), "+f"(c[2]), "+f"(c[3])
        : "r"(a[0]), "r"(a[1]), "r"(a[2]), "r"(a[3]), "r"(b[0]), "r"(b[1]));
}

// ---------------------------------------------------------------- kernels
// W[512][128] -> WT fp16 [128][512]; resets the ticket.
__global__ void transposeW_kernel(const float* __restrict__ W, __half* __restrict__ WT) {
    if (blockIdx.x == 0 && threadIdx.x == 0) g_ticket = 0u;
    int t = blockIdx.x * blockDim.x + threadIdx.x;   // 65536 threads
    int k = t >> 7, n = t & 127;
    WT[(size_t)n * D_IN + k] = __float2half_rn(W[(size_t)k * D_OUT + n]);
}

// C-tile(128x128) = A[128,K](fp32) @ B[128,K](fp16)^T.  128 threads, warp grid 2x2,
// warp tile 64x64.  A: LDG->regs->fp16 STS (2-stage ring, stored one chunk ahead).
// B: cp.async 4-stage ring.  QUEUE: persistent ticket (mt,ks) -> g_part.
// TRANS_EPI: write C^T as fp16 (xT for GEMM2).
template <bool TRANS_EPI, bool QUEUE>
__global__ void __launch_bounds__(128, 2)
gemm_f16(const float* __restrict__ A, const __half* __restrict__ B,
         float* __restrict__ C, int K, int nchunks)
{
    extern __shared__ __align__(16) char smem[];
    __shared__ unsigned s_unit;
    const uint32_t sA = smem_u32(smem);                  // 2 fp16 A stages
    const uint32_t sB = sA + A_STAGES * TILE_B;          // 4 fp16 B stages
    const int tid  = threadIdx.x;
    const int wid  = tid >> 5, lane = tid & 31;
    const int mw   = (wid >> 1) * 64;                    // 2 m warp-groups
    const int nw   = (wid & 1)  * 64;                    // 2 n warp-groups
    const int rg   = lane >> 2;                          // mma row group
    const int cc   = (lane & 3) * 2;                     // mma col pair base
    // ldmatrix per-lane address components
    const int a_r  = (lane & 7) + ((lane >> 3) & 1) * 8; // A: groups 1,3 -> +8 rows
    const int a_k  = (lane >> 4) * 16;                   // A: groups 2,3 -> +16B k
    const int b_r  = (lane & 7) + ((lane >> 4) & 1) * 8; // B: groups 2,3 -> +8 rows
    const int b_k  = ((lane >> 3) & 1) * 16;             // B: groups 1,3 -> +16B k
    // A LDG/STS granules: 8 x 16B fp32 -> 8 x 8B fp16 per thread
    int arow[8], acol[8];
#pragma unroll
    for (int g = 0; g < 8; ++g) { int idx = tid + 128 * g; arow[g] = idx >> 3; acol[g] = idx & 7; }
    // B cp.async granules: 4 x 16B fp16 per thread
    int brow[4], bcol[4];
#pragma unroll
    for (int g = 0; g < 4; ++g) { int idx = tid + 128 * g; brow[g] = idx >> 2; bcol[g] = idx & 3; }

    for (;;) {
        int mt, ks;
        if (QUEUE) {
            if (tid == 0) s_unit = atomicAdd(&g_ticket, 1u);
            __syncthreads();
            unsigned u = s_unit;
            if (u >= (unsigned)UNITS) return;
            mt = (int)(u & 127u); ks = (int)(u >> 7);
        } else {
            mt = blockIdx.x; ks = 0;
        }

        const float*  a0 = A + (size_t)mt * 128 * K + (size_t)ks * CH_UNIT * KCHUNK;
        const __half* b0 = B + (size_t)ks * CH_UNIT * KCHUNK;

        auto ldg_A = [&](int chunk, float4* st) {
            const float* ga = a0 + (size_t)chunk * KCHUNK;
#pragma unroll
            for (int g = 0; g < 8; ++g)
                st[g] = *(const float4*)(ga + (size_t)arow[g] * K + acol[g] * 4);
        };
        auto sts_A = [&](int chunk, const float4* st) {
            uint32_t abuf = sA + (chunk & 1) * TILE_B;
#pragma unroll
            for (int g = 0; g < 8; ++g) {
                uint32_t w0 = pack_h2(st[g].x, st[g].y);
                uint32_t w1 = pack_h2(st[g].z, st[g].w);
                sts64(abuf + arow[g] * ROW_B + acol[g] * 8, w0, w1);
            }
        };
        auto cp_B = [&](int chunk) {
            const __half* gb = b0 + (size_t)chunk * KCHUNK;
            uint32_t dst = sB + (chunk & (B_STAGES - 1)) * TILE_B;
#pragma unroll
            for (int g = 0; g < 4; ++g)
                cp16(dst + brow[g] * ROW_B + bcol[g] * 16,
                     gb + (size_t)brow[g] * K + bcol[g] * 8);
        };

        float acc[4][8][4];
#pragma unroll
        for (int i = 0; i < 4; ++i)
#pragma unroll
            for (int j = 0; j < 8; ++j)
#pragma unroll
                for (int f = 0; f < 4; ++f) acc[i][j][f] = 0.f;

        float4 st[8];
        ldg_A(0, st);
        sts_A(0, st);                       // stage 0; drained by first sync
        if (nchunks > 1) ldg_A(1, st);      // held in regs until iter 0
        cp_B(0); asm volatile("cp.async.commit_group;" ::: "memory");
        if (nchunks > 1) cp_B(1);
        asm volatile("cp.async.commit_group;" ::: "memory");
        if (nchunks > 2) cp_B(2);
        asm volatile("cp.async.commit_group;" ::: "memory");

        for (int kc = 0; kc < nchunks; ++kc) {
            asm volatile("cp.async.wait_group 2;" ::: "memory");   // B(kc) ready
            __syncthreads();   // readers of stage (kc+1)&1 done; A(kc)/B(kc) visible
            // A(kc+1) -> stage (kc+1)&1 (regs loaded last iteration)
            if (kc + 1 < nchunks) sts_A(kc + 1, st);
            if (kc + 2 < nchunks) ldg_A(kc + 2, st);
            if (kc + 3 < nchunks) cp_B(kc + 3);
            asm volatile("cp.async.commit_group;" ::: "memory");

            const uint32_t abuf = sA + (kc & 1) * TILE_B;
            const uint32_t bbuf = sB + (kc & (B_STAGES - 1)) * TILE_B;
#pragma unroll
            for (int kk = 0; kk < 2; ++kk) {
                uint32_t a[4][4];
#pragma unroll
                for (int i = 0; i < 4; ++i)
                    ldsm4(a[i], abuf + (mw + i * 16 + a_r) * ROW_B + a_k + kk * 32);
                uint32_t b[4][4];
#pragma unroll
                for (int jp = 0; jp < 4; ++jp)
                    ldsm4(b[jp], bbuf + (nw + jp * 16 + b_r) * ROW_B + b_k + kk * 32);
#pragma unroll
                for (int i = 0; i < 4; ++i)
#pragma unroll
                    for (int j = 0; j < 8; ++j)
                        mma_f16(acc[i][j], a[i], &b[j >> 1][(j & 1) * 2]);
            }
        }

        // Epilogue
#pragma unroll
        for (int i = 0; i < 4; ++i) {
            const int rloc = mw + i * 16 + rg;
#pragma unroll
            for (int j = 0; j < 8; ++j) {
                const int col = nw + j * 8 + cc;
                if (TRANS_EPI) {           // write x^T as fp16
                    __half* X = reinterpret_cast<__half*>(C);
                    const int grow = mt * 128 + rloc;
                    X[(size_t)col       * M_TOTAL + grow]     = __float2half_rn(acc[i][j][0]);
                    X[(size_t)(col + 1) * M_TOTAL + grow]     = __float2half_rn(acc[i][j][1]);
                    X[(size_t)col       * M_TOTAL + grow + 8] = __float2half_rn(acc[i][j][2]);
                    X[(size_t)(col + 1) * M_TOTAL + grow + 8] = __float2half_rn(acc[i][j][3]);
                } else {
                    float* cb = C + (size_t)ks * M_TOTAL * D_OUT + (size_t)mt * 128 * D_OUT;
                    *(float2*)(cb + (size_t)rloc * D_OUT + col) =
                        make_float2(acc[i][j][0], acc[i][j][1]);
                    *(float2*)(cb + (size_t)(rloc + 8) * D_OUT + col) =
                        make_float2(acc[i][j][2], acc[i][j][3]);
                }
            }
        }
        if (!QUEUE) return;
        __syncthreads();   // all lanes done with s_unit before next ticket write
    }
}

// out = sum over KSPLIT partials
__global__ void reduce_kernel(float* __restrict__ out) {
    const size_t i = (size_t)blockIdx.x * blockDim.x + threadIdx.x;  // 524288 f4
    const float4* p = reinterpret_cast<const float4*>(g_part);
    const size_t stride = (size_t)M_TOTAL * D_OUT / 4;
    float4 s = p[i];
#pragma unroll
    for (int k = 1; k < KSPLIT; ++k) {
        float4 t = p[i + (size_t)k * stride];
        s.x += t.x; s.y += t.y; s.z += t.z; s.w += t.w;
    }
    reinterpret_cast<float4*>(out)[i] = s;
}

// ---------------------------------------------------------------- launch
extern "C" void kernel_launch(void* const* d_in, const int* in_sizes, int n_in,
                              void* d_out, int out_size)
{
    const float* inputs = nullptr;
    const float* adj = nullptr;
    const float* weights = nullptr;
    for (int i = 0; i < n_in; ++i) {
        long sz = (long)in_sizes[i];
        if (sz == (long)M_TOTAL * D_IN)         inputs  = (const float*)d_in[i];
        else if (sz == (long)M_TOTAL * M_TOTAL) adj     = (const float*)d_in[i];
        else if (sz == (long)D_IN * D_OUT)      weights = (const float*)d_in[i];
    }

    __half *xT = nullptr, *WT = nullptr;
    float  *part = nullptr;
    cudaGetSymbolAddress((void**)&xT, g_xT);
    cudaGetSymbolAddress((void**)&WT, g_WT);
    cudaGetSymbolAddress((void**)&part, g_part);
    cudaFuncSetAttribute((const void*)gemm_f16<true,  false>,
                         cudaFuncAttributeMaxDynamicSharedMemorySize, SMEM_BYTES);
    cudaFuncSetAttribute((const void*)gemm_f16<false, true>,
                         cudaFuncAttributeMaxDynamicSharedMemorySize, SMEM_BYTES);

    // 1) WT = fp16(W^T); reset ticket
    transposeW_kernel<<<(D_IN * D_OUT) / 256, 256>>>(weights, WT);
    // 2) xT = fp16((inputs @ W)^T)
    gemm_f16<true,  false><<<M_TOTAL / 128, 128, SMEM_BYTES>>>(
        inputs, WT, (float*)xT, D_IN, D_IN / KCHUNK);
    // 3) partials = adj @ x  (persistent, split-K=8)
    gemm_f16<false, true><<<296, 128, SMEM_BYTES>>>(
        adj, xT, part, M_TOTAL, CH_UNIT);
    // 4) out = sum partials
    reduce_kernel<<<(M_TOTAL * D_OUT / 4) / 256, 256>>>((float*)d_out);
}